// round 2
// baseline (speedup 1.0000x reference)
#include <cuda_runtime.h>
#include <cstdint>
#include <cstddef>

#define N_NODES 10000
#define N_EDGES 160000
#define D_IN 512

// ---------------- scratch (static __device__ — no allocations) ----------------
__device__ float g_Y [N_NODES * 256];   // x @ W_l
__device__ float g_R [N_NODES * 256];   // x @ W_r
__device__ float g_H [N_NODES * 256];   // SAGE output (post relu)
__device__ float g_H2[N_NODES * 128];
__device__ float g_H3[N_NODES * 64];
__device__ float g_H4[N_NODES * 32];
__device__ float4 g_F [N_NODES];        // (h0,h1,h2, sqnorm)
__device__ int   g_cnt[N_NODES];
__device__ int   g_off[N_NODES + 1];
__device__ int   g_cur[N_NODES];
__device__ int   g_csr[N_EDGES];
__device__ int   g_is64;

// ---------------- edge dtype detection + CSR build ----------------
__global__ void init_kernel() {
    int i = blockIdx.x * blockDim.x + threadIdx.x;
    if (i < N_NODES) g_cnt[i] = 0;
    if (i == 0) g_is64 = 1;
}

// Interpret first N_EDGES elements as int64. True int64 indices are all in
// [0, N_NODES). An int32 buffer reinterpreted as int64 gives lo + (hi<<32)
// with hi = the next random index -> out of range almost surely. Any
// out-of-range value flips the flag to "int32".
// (Scanning N_EDGES int64 = 1.28MB is within the buffer for BOTH dtypes.)
__global__ void detect_kernel(const long long* __restrict__ ei) {
    int e = blockIdx.x * blockDim.x + threadIdx.x;
    if (e < N_EDGES) {
        long long v = ei[e];
        if (v < 0 || v >= N_NODES) g_is64 = 0;
    }
}

__device__ __forceinline__ void load_edge(const void* eiv, int e, int& s, int& d) {
    if (g_is64) {
        const long long* p = (const long long*)eiv;
        s = (int)p[e];
        d = (int)p[N_EDGES + e];
    } else {
        const int* p = (const int*)eiv;
        s = p[e];
        d = p[N_EDGES + e];
    }
}

__global__ void count_kernel(const void* __restrict__ eiv) {
    int e = blockIdx.x * blockDim.x + threadIdx.x;
    if (e < N_EDGES) {
        int s, d;
        load_edge(eiv, e, s, d);
        atomicAdd(&g_cnt[d], 1);
    }
}

__global__ void scan_kernel() {
    // single block, 1024 threads, 10 elems each
    const int CHUNK = (N_NODES + 1023) / 1024;   // 10
    __shared__ int ssum[1024];
    int t = threadIdx.x;
    int base = t * CHUNK;
    int local[CHUNK];
    int s = 0;
#pragma unroll
    for (int i = 0; i < CHUNK; i++) {
        int idx = base + i;
        int v = (idx < N_NODES) ? g_cnt[idx] : 0;
        local[i] = v;
        s += v;
    }
    ssum[t] = s;
    __syncthreads();
    // Hillis-Steele inclusive scan over 1024 partials
    for (int off = 1; off < 1024; off <<= 1) {
        int v = 0;
        if (t >= off) v = ssum[t - off];
        __syncthreads();
        if (t >= off) ssum[t] += v;
        __syncthreads();
    }
    int pre = (t == 0) ? 0 : ssum[t - 1];
#pragma unroll
    for (int i = 0; i < CHUNK; i++) {
        int idx = base + i;
        if (idx < N_NODES) {
            g_off[idx] = pre;
            g_cur[idx] = pre;
            pre += local[i];
        }
    }
    if (t == 1023) g_off[N_NODES] = ssum[1023];
}

__global__ void scatter_kernel(const void* __restrict__ eiv) {
    int e = blockIdx.x * blockDim.x + threadIdx.x;
    if (e < N_EDGES) {
        int s, d;
        load_edge(eiv, e, s, d);
        int p = atomicAdd(&g_cur[d], 1);
        g_csr[p] = s;
    }
}

// ---------------- generic fp32 tiled GEMM  C = A[M,K] @ B[K,N] (+bias,+relu) ----------------
// BM=128, BK=16, 256 threads (16x16), thread tile TM=8 x TN=(BN/16)
template <int BN, int TN>
__global__ __launch_bounds__(256)
void gemm_kernel(const float* __restrict__ A, const float* __restrict__ B,
                 const float* __restrict__ bias, float* __restrict__ C,
                 int M, int K, int Ncols, int relu)
{
    constexpr int BM = 128, BK = 16, TM = 8;
    __shared__ float As[BM][BK + 4];   // +4 pad: keeps rows 16B aligned (20 floats = 80B)
    __shared__ float Bs[BK][BN];

    int tid = threadIdx.x;
    int tx = tid & 15;        // col group 0..15
    int ty = tid >> 4;        // row group 0..15
    int bm0 = blockIdx.y * BM;
    int bn0 = blockIdx.x * BN;

    float acc[TM][TN];
#pragma unroll
    for (int i = 0; i < TM; i++)
#pragma unroll
        for (int j = 0; j < TN; j++) acc[i][j] = 0.f;

    for (int k0 = 0; k0 < K; k0 += BK) {
        // load A tile (128x16) as 512 float4, 2 per thread
#pragma unroll
        for (int l = 0; l < 2; l++) {
            int idx = tid + l * 256;
            int r = idx >> 2;
            int q = idx & 3;
            int row = bm0 + r;
            float4 v;
            if (row < M)
                v = *(const float4*)(A + (size_t)row * K + k0 + q * 4);
            else
                v = make_float4(0.f, 0.f, 0.f, 0.f);
            *(float4*)&As[r][q * 4] = v;
        }
        // load B tile (16 x BN)
#pragma unroll
        for (int idx = tid; idx < BK * BN; idx += 256) {
            int r = idx / BN;
            int c = idx % BN;
            Bs[r][c] = B[(size_t)(k0 + r) * Ncols + bn0 + c];
        }
        __syncthreads();

#pragma unroll
        for (int k = 0; k < BK; k++) {
            float a[TM], b[TN];
#pragma unroll
            for (int i = 0; i < TM; i++) a[i] = As[ty + 16 * i][k];
#pragma unroll
            for (int j = 0; j < TN; j++) b[j] = Bs[k][tx + 16 * j];
#pragma unroll
            for (int i = 0; i < TM; i++)
#pragma unroll
                for (int j = 0; j < TN; j++) acc[i][j] += a[i] * b[j];
        }
        __syncthreads();
    }

#pragma unroll
    for (int i = 0; i < TM; i++) {
        int row = bm0 + ty + 16 * i;
        if (row >= M) continue;
#pragma unroll
        for (int j = 0; j < TN; j++) {
            int col = bn0 + tx + 16 * j;
            float v = acc[i][j];
            if (bias) v += bias[col];
            if (relu) v = fmaxf(v, 0.f);
            C[(size_t)row * Ncols + col] = v;
        }
    }
}

// ---------------- aggregation: H = relu(segsum(Y[src])/max(deg,1) + b_l + R) ----------------
__global__ void aggr_kernel(const float* __restrict__ b_l) {
    int warp = (blockIdx.x * blockDim.x + threadIdx.x) >> 5;
    int lane = threadIdx.x & 31;
    if (warp >= N_NODES) return;
    int s0 = g_off[warp], s1 = g_off[warp + 1];

    float4 a0 = make_float4(0.f, 0.f, 0.f, 0.f);
    float4 a1 = a0;
    const float4* Y4 = (const float4*)g_Y;
    for (int e = s0; e < s1; e++) {
        int s = g_csr[e];
        float4 v0 = Y4[(size_t)s * 64 + lane];
        float4 v1 = Y4[(size_t)s * 64 + 32 + lane];
        a0.x += v0.x; a0.y += v0.y; a0.z += v0.z; a0.w += v0.w;
        a1.x += v1.x; a1.y += v1.y; a1.z += v1.z; a1.w += v1.w;
    }
    int deg = s1 - s0;
    float inv = (deg > 0) ? 1.0f / (float)deg : 1.0f;

    const float4* R4 = (const float4*)g_R;
    const float4* BL = (const float4*)b_l;
    float4* H4 = (float4*)g_H;

    float4 r0 = R4[(size_t)warp * 64 + lane];
    float4 r1 = R4[(size_t)warp * 64 + 32 + lane];
    float4 bl0 = BL[lane];
    float4 bl1 = BL[lane + 32];

    float4 o0, o1;
    o0.x = fmaxf(a0.x * inv + bl0.x + r0.x, 0.f);
    o0.y = fmaxf(a0.y * inv + bl0.y + r0.y, 0.f);
    o0.z = fmaxf(a0.z * inv + bl0.z + r0.z, 0.f);
    o0.w = fmaxf(a0.w * inv + bl0.w + r0.w, 0.f);
    o1.x = fmaxf(a1.x * inv + bl1.x + r1.x, 0.f);
    o1.y = fmaxf(a1.y * inv + bl1.y + r1.y, 0.f);
    o1.z = fmaxf(a1.z * inv + bl1.z + r1.z, 0.f);
    o1.w = fmaxf(a1.w * inv + bl1.w + r1.w, 0.f);
    H4[(size_t)warp * 64 + lane] = o0;
    H4[(size_t)warp * 64 + 32 + lane] = o1;
}

// ---------------- final layer: F = H4 @ W3 + b3, plus squared norm ----------------
__global__ void final_kernel(const float* __restrict__ W3, const float* __restrict__ b3) {
    int n = blockIdx.x * blockDim.x + threadIdx.x;
    if (n >= N_NODES) return;
    float a0 = b3[0], a1 = b3[1], a2 = b3[2];
    const float* h = g_H4 + (size_t)n * 32;
#pragma unroll
    for (int k = 0; k < 32; k++) {
        float hv = h[k];
        a0 += hv * W3[k * 3 + 0];
        a1 += hv * W3[k * 3 + 1];
        a2 += hv * W3[k * 3 + 2];
    }
    g_F[n] = make_float4(a0, a1, a2, a0 * a0 + a1 * a1 + a2 * a2);
}

// ---------------- pairwise L2 (reference norm-trick semantics) ----------------
__device__ __forceinline__ float pdist(float4 a, float4 b) {
    float d2 = a.w + b.w - 2.0f * (a.x * b.x + a.y * b.y + a.z * b.z);
    if (d2 <= 0.f) return 0.f;
    float r;
    asm("sqrt.approx.f32 %0, %1;" : "=f"(r) : "f"(d2));
    return r;
}

__global__ __launch_bounds__(256)
void dist_kernel(float* __restrict__ out) {
    __shared__ float4 si[128], sj[128];
    int bi = blockIdx.y * 128, bj = blockIdx.x * 128;
    int t = threadIdx.x;
    if (t < 128) {
        int i = bi + t;
        si[t] = (i < N_NODES) ? g_F[i] : make_float4(0.f, 0.f, 0.f, 0.f);
    } else {
        int j = bj + t - 128;
        sj[t - 128] = (j < N_NODES) ? g_F[j] : make_float4(0.f, 0.f, 0.f, 0.f);
    }
    __syncthreads();

    int c4 = t & 31;     // 32 float4-columns
    int rb = t >> 5;     // 8 row groups of 16
    int j0 = bj + c4 * 4;
    if (j0 >= N_NODES) return;      // N_NODES % 4 == 0 -> all 4 cols valid

    float4 b0 = sj[c4 * 4 + 0];
    float4 b1 = sj[c4 * 4 + 1];
    float4 b2 = sj[c4 * 4 + 2];
    float4 b3 = sj[c4 * 4 + 3];

#pragma unroll 4
    for (int rr = 0; rr < 16; rr++) {
        int r = rb * 16 + rr;
        int i = bi + r;
        if (i >= N_NODES) break;
        float4 a = si[r];
        float4 o;
        o.x = pdist(a, b0);
        o.y = pdist(a, b1);
        o.z = pdist(a, b2);
        o.w = pdist(a, b3);
        *(float4*)(out + (size_t)i * N_NODES + j0) = o;
    }
}

// ---------------- launch ----------------
extern "C" void kernel_launch(void* const* d_in, const int* in_sizes, int n_in,
                              void* d_out, int out_size)
{
    const float*     x   = (const float*)d_in[0];
    const void*      ei  = d_in[1];                 // int32 or int64, detected on-device
    const float*     W_l = (const float*)d_in[2];
    const float*     b_l = (const float*)d_in[3];
    const float*     W_r = (const float*)d_in[4];
    const float*     Wa  = (const float*)d_in[5];
    const float*     ba  = (const float*)d_in[6];
    const float*     W1  = (const float*)d_in[7];
    const float*     b1  = (const float*)d_in[8];
    const float*     W2  = (const float*)d_in[9];
    const float*     b2  = (const float*)d_in[10];
    const float*     W3  = (const float*)d_in[11];
    const float*     b3  = (const float*)d_in[12];
    float* out = (float*)d_out;

    float *pY, *pR, *pH, *pH2, *pH3, *pH4;
    cudaGetSymbolAddress((void**)&pY,  g_Y);
    cudaGetSymbolAddress((void**)&pR,  g_R);
    cudaGetSymbolAddress((void**)&pH,  g_H);
    cudaGetSymbolAddress((void**)&pH2, g_H2);
    cudaGetSymbolAddress((void**)&pH3, g_H3);
    cudaGetSymbolAddress((void**)&pH4, g_H4);

    // CSR build (dtype-robust)
    init_kernel<<<(N_NODES + 255) / 256, 256>>>();
    detect_kernel<<<(N_EDGES + 255) / 256, 256>>>((const long long*)ei);
    count_kernel<<<(N_EDGES + 255) / 256, 256>>>(ei);
    scan_kernel<<<1, 1024>>>();
    scatter_kernel<<<(N_EDGES + 255) / 256, 256>>>(ei);

    const int MBLK = (N_NODES + 127) / 128;   // 79

    // Y = x @ W_l ; R = x @ W_r   (N=256, K=512)
    gemm_kernel<128, 8><<<dim3(2, MBLK), 256>>>(x, W_l, nullptr, pY, N_NODES, 512, 256, 0);
    gemm_kernel<128, 8><<<dim3(2, MBLK), 256>>>(x, W_r, nullptr, pR, N_NODES, 512, 256, 0);

    // H = relu(segmean(Y) + b_l + R)
    aggr_kernel<<<(N_NODES * 32 + 255) / 256, 256>>>(b_l);

    // MLP
    gemm_kernel<128, 8><<<dim3(1, MBLK), 256>>>(pH,  Wa, ba, pH2, N_NODES, 256, 128, 1);
    gemm_kernel<64, 4><<<dim3(1, MBLK), 256>>>(pH2, W1, b1, pH3, N_NODES, 128, 64, 1);
    gemm_kernel<32, 2><<<dim3(1, MBLK), 256>>>(pH3, W2, b2, pH4, N_NODES, 64, 32, 1);
    final_kernel<<<(N_NODES + 255) / 256, 256>>>(W3, b3);

    // pairwise distances
    dist_kernel<<<dim3(MBLK, MBLK), 256>>>(out);

    (void)in_sizes; (void)n_in; (void)out_size;
}

// round 4
// speedup vs baseline: 1.1439x; 1.1439x over previous
#include <cuda_runtime.h>
#include <cstdint>
#include <cstddef>

#define N_NODES 10000
#define N_EDGES 160000
typedef unsigned long long ull;

// ---------------- scratch (static __device__ — no allocations) ----------------
__device__ float g_Y [N_NODES * 256];   // x @ W_l
__device__ float g_R [N_NODES * 256];   // x @ W_r
__device__ float g_H [N_NODES * 256];   // SAGE output (post relu)
__device__ float g_H2[N_NODES * 128];
__device__ float g_H3[N_NODES * 64];
__device__ float g_H4[N_NODES * 32];
__device__ float4 g_F [N_NODES];
__device__ int   g_cnt[N_NODES];
__device__ int   g_off[N_NODES + 1];
__device__ int   g_cur[N_NODES];
__device__ int   g_csr[N_EDGES];
__device__ int   g_is64;

// ---------------- edge dtype detection + CSR build ----------------
__global__ void init_kernel() {
    int i = blockIdx.x * blockDim.x + threadIdx.x;
    if (i < N_NODES) g_cnt[i] = 0;
    if (i == 0) g_is64 = 1;
}
__global__ void detect_kernel(const long long* __restrict__ ei) {
    int e = blockIdx.x * blockDim.x + threadIdx.x;
    if (e < N_EDGES) {
        long long v = ei[e];
        if (v < 0 || v >= N_NODES) g_is64 = 0;
    }
}
__device__ __forceinline__ void load_edge(const void* eiv, int e, int& s, int& d) {
    if (g_is64) {
        const long long* p = (const long long*)eiv;
        s = (int)p[e]; d = (int)p[N_EDGES + e];
    } else {
        const int* p = (const int*)eiv;
        s = p[e]; d = p[N_EDGES + e];
    }
}
__global__ void count_kernel(const void* __restrict__ eiv) {
    int e = blockIdx.x * blockDim.x + threadIdx.x;
    if (e < N_EDGES) { int s, d; load_edge(eiv, e, s, d); atomicAdd(&g_cnt[d], 1); }
}

__global__ void scan_kernel() {
    const int CHUNK = (N_NODES + 1023) / 1024;   // 10
    __shared__ int wsum[32];
    int t = threadIdx.x;
    int lane = t & 31, w = t >> 5;
    int base = t * CHUNK;
    int local[CHUNK];
    int s = 0;
#pragma unroll
    for (int i = 0; i < CHUNK; i++) {
        int idx = base + i;
        int v = (idx < N_NODES) ? g_cnt[idx] : 0;
        local[i] = v; s += v;
    }
    int v = s;
#pragma unroll
    for (int o = 1; o < 32; o <<= 1) {
        int u = __shfl_up_sync(0xFFFFFFFFu, v, o);
        if (lane >= o) v += u;
    }
    if (lane == 31) wsum[w] = v;
    __syncthreads();
    if (w == 0) {
        int x2 = wsum[lane];
#pragma unroll
        for (int o = 1; o < 32; o <<= 1) {
            int u = __shfl_up_sync(0xFFFFFFFFu, x2, o);
            if (lane >= o) x2 += u;
        }
        wsum[lane] = x2;
    }
    __syncthreads();
    int pre = v - s + (w > 0 ? wsum[w - 1] : 0);
#pragma unroll
    for (int i = 0; i < CHUNK; i++) {
        int idx = base + i;
        if (idx < N_NODES) {
            g_off[idx] = pre; g_cur[idx] = pre;
            pre += local[i];
        }
    }
    if (t == 1023) g_off[N_NODES] = wsum[31];
}

__global__ void scatter_kernel(const void* __restrict__ eiv) {
    int e = blockIdx.x * blockDim.x + threadIdx.x;
    if (e < N_EDGES) {
        int s, d; load_edge(eiv, e, s, d);
        int p = atomicAdd(&g_cur[d], 1);
        g_csr[p] = s;
    }
}

// ---------------- fp32 tiled GEMM with packed f32x2 FMA ----------------
// C = A[M,K] @ B[K,N] (+bias,+relu). BM=128, BK=16, 256 threads.
// Thread (tx=tid&15, ty=tid>>4) computes rows ty*8..ty*8+7 (4 row-pairs) x TN cols (tx+16j).
// A tile stored transposed AsT[k][row], row stride 136 floats (bank-conflict-free scatter).
template <int BN, int TN>
__global__ __launch_bounds__(256)
void gemm_kernel(const float* __restrict__ A, const float* __restrict__ B,
                 const float* __restrict__ bias, float* __restrict__ C,
                 int M, int K, int Ncols, int relu)
{
    constexpr int BM = 128, BK = 16;
    constexpr int ASTRIDE = 136;
    __shared__ float AsT[BK][ASTRIDE];
    __shared__ float Bs[BK][BN];

    int tid = threadIdx.x;
    int tx = tid & 15;
    int ty = tid >> 4;
    int bm0 = blockIdx.y * BM;
    int bn0 = blockIdx.x * BN;

    ull acc2[4][TN];
#pragma unroll
    for (int i = 0; i < 4; i++)
#pragma unroll
        for (int j = 0; j < TN; j++) acc2[i][j] = 0ull;

    for (int k0 = 0; k0 < K; k0 += BK) {
        // load A tile (128 rows x 16 k) -> transposed into AsT
#pragma unroll
        for (int l = 0; l < 2; l++) {
            int idx = tid + l * 256;
            int r = idx >> 2, q = idx & 3;
            int row = bm0 + r;
            float4 v = make_float4(0.f, 0.f, 0.f, 0.f);
            if (row < M) v = *(const float4*)(A + (size_t)row * K + k0 + q * 4);
            AsT[q * 4 + 0][r] = v.x;
            AsT[q * 4 + 1][r] = v.y;
            AsT[q * 4 + 2][r] = v.z;
            AsT[q * 4 + 3][r] = v.w;
        }
        // load B tile (16 x BN)
#pragma unroll
        for (int idx = tid; idx < BK * BN; idx += 256) {
            int r = idx / BN, cc = idx % BN;
            Bs[r][cc] = B[(size_t)(k0 + r) * Ncols + bn0 + cc];
        }
        __syncthreads();

#pragma unroll
        for (int k = 0; k < BK; k++) {
            const ulonglong2* ap = (const ulonglong2*)&AsT[k][ty * 8];
            ulonglong2 a01 = ap[0];
            ulonglong2 a23 = ap[1];
            ull av[4] = { a01.x, a01.y, a23.x, a23.y };
            ull bv[TN];
#pragma unroll
            for (int j = 0; j < TN; j++) {
                unsigned bu = __float_as_uint(Bs[k][tx + 16 * j]);
                asm("mov.b64 %0, {%1, %1};" : "=l"(bv[j]) : "r"(bu));
            }
#pragma unroll
            for (int i = 0; i < 4; i++)
#pragma unroll
                for (int j = 0; j < TN; j++)
                    asm("fma.rn.f32x2 %0, %1, %2, %0;"
                        : "+l"(acc2[i][j]) : "l"(av[i]), "l"(bv[j]));
        }
        __syncthreads();
    }

#pragma unroll
    for (int i = 0; i < 4; i++) {
#pragma unroll
        for (int p = 0; p < 2; p++) {
            int row = bm0 + ty * 8 + 2 * i + p;
            if (row >= M) continue;
#pragma unroll
            for (int j = 0; j < TN; j++) {
                ull u = acc2[i][j];
                float v = __uint_as_float(p ? (unsigned)(u >> 32) : (unsigned)u);
                int col = bn0 + tx + 16 * j;
                if (bias) v += bias[col];
                if (relu) v = fmaxf(v, 0.f);
                C[(size_t)row * Ncols + col] = v;
            }
        }
    }
}

// ---------------- aggregation: H = relu(segmean(Y) + b_l + R) ----------------
__global__ void aggr_kernel(const float* __restrict__ b_l) {
    int warp = (blockIdx.x * blockDim.x + threadIdx.x) >> 5;
    int lane = threadIdx.x & 31;
    if (warp >= N_NODES) return;
    int s0 = g_off[warp], s1 = g_off[warp + 1];

    float4 a0 = make_float4(0.f, 0.f, 0.f, 0.f);
    float4 a1 = a0;
    const float4* Y4 = (const float4*)g_Y;
    for (int e = s0; e < s1; e++) {
        int s = g_csr[e];
        float4 v0 = Y4[(size_t)s * 64 + lane];
        float4 v1 = Y4[(size_t)s * 64 + 32 + lane];
        a0.x += v0.x; a0.y += v0.y; a0.z += v0.z; a0.w += v0.w;
        a1.x += v1.x; a1.y += v1.y; a1.z += v1.z; a1.w += v1.w;
    }
    int deg = s1 - s0;
    float inv = (deg > 0) ? 1.0f / (float)deg : 1.0f;

    const float4* R4 = (const float4*)g_R;
    const float4* BL = (const float4*)b_l;
    float4* H4 = (float4*)g_H;

    float4 r0 = R4[(size_t)warp * 64 + lane];
    float4 r1 = R4[(size_t)warp * 64 + 32 + lane];
    float4 bl0 = BL[lane];
    float4 bl1 = BL[lane + 32];

    float4 o0, o1;
    o0.x = fmaxf(a0.x * inv + bl0.x + r0.x, 0.f);
    o0.y = fmaxf(a0.y * inv + bl0.y + r0.y, 0.f);
    o0.z = fmaxf(a0.z * inv + bl0.z + r0.z, 0.f);
    o0.w = fmaxf(a0.w * inv + bl0.w + r0.w, 0.f);
    o1.x = fmaxf(a1.x * inv + bl1.x + r1.x, 0.f);
    o1.y = fmaxf(a1.y * inv + bl1.y + r1.y, 0.f);
    o1.z = fmaxf(a1.z * inv + bl1.z + r1.z, 0.f);
    o1.w = fmaxf(a1.w * inv + bl1.w + r1.w, 0.f);
    H4[(size_t)warp * 64 + lane] = o0;
    H4[(size_t)warp * 64 + 32 + lane] = o1;
}

// ---------------- final layer ----------------
__global__ void final_kernel(const float* __restrict__ W3, const float* __restrict__ b3) {
    int n = blockIdx.x * blockDim.x + threadIdx.x;
    if (n >= N_NODES) return;
    float a0 = b3[0], a1 = b3[1], a2 = b3[2];
    const float* h = g_H4 + (size_t)n * 32;
#pragma unroll
    for (int k = 0; k < 32; k++) {
        float hv = h[k];
        a0 += hv * W3[k * 3 + 0];
        a1 += hv * W3[k * 3 + 1];
        a2 += hv * W3[k * 3 + 2];
    }
    g_F[n] = make_float4(a0, a1, a2, a0 * a0 + a1 * a1 + a2 * a2);
}

// ---------------- pairwise L2 ----------------
__device__ __forceinline__ float pdist(float4 a, float4 b) {
    float d2 = a.w + b.w - 2.0f * (a.x * b.x + a.y * b.y + a.z * b.z);
    if (d2 <= 0.f) return 0.f;
    float r;
    asm("sqrt.approx.f32 %0, %1;" : "=f"(r) : "f"(d2));
    return r;
}

__global__ __launch_bounds__(256)
void dist_kernel(float* __restrict__ out) {
    __shared__ float4 si[128], sj[128];
    int bi = blockIdx.y * 128, bj = blockIdx.x * 128;
    int t = threadIdx.x;
    if (t < 128) {
        int i = bi + t;
        si[t] = (i < N_NODES) ? g_F[i] : make_float4(0.f, 0.f, 0.f, 0.f);
    } else {
        int j = bj + t - 128;
        sj[t - 128] = (j < N_NODES) ? g_F[j] : make_float4(0.f, 0.f, 0.f, 0.f);
    }
    __syncthreads();

    int c4 = t & 31;
    int rb = t >> 5;
    int j0 = bj + c4 * 4;
    if (j0 >= N_NODES) return;

    float4 b0 = sj[c4 * 4 + 0];
    float4 b1 = sj[c4 * 4 + 1];
    float4 b2 = sj[c4 * 4 + 2];
    float4 b3 = sj[c4 * 4 + 3];

#pragma unroll 4
    for (int rr = 0; rr < 16; rr++) {
        int r = rb * 16 + rr;
        int i = bi + r;
        if (i >= N_NODES) break;
        float4 a = si[r];
        float4 o;
        o.x = pdist(a, b0);
        o.y = pdist(a, b1);
        o.z = pdist(a, b2);
        o.w = pdist(a, b3);
        *(float4*)(out + (size_t)i * N_NODES + j0) = o;
    }
}

// ---------------- launch ----------------
extern "C" void kernel_launch(void* const* d_in, const int* in_sizes, int n_in,
                              void* d_out, int out_size)
{
    const float* x   = (const float*)d_in[0];
    const void*  ei  = d_in[1];
    const float* W_l = (const float*)d_in[2];
    const float* b_l = (const float*)d_in[3];
    const float* W_r = (const float*)d_in[4];
    const float* Wa  = (const float*)d_in[5];
    const float* ba  = (const float*)d_in[6];
    const float* W1  = (const float*)d_in[7];
    const float* b1  = (const float*)d_in[8];
    const float* W2  = (const float*)d_in[9];
    const float* b2  = (const float*)d_in[10];
    const float* W3  = (const float*)d_in[11];
    const float* b3  = (const float*)d_in[12];
    float* out = (float*)d_out;

    float *pY, *pR, *pH, *pH2, *pH3, *pH4;
    cudaGetSymbolAddress((void**)&pY,  g_Y);
    cudaGetSymbolAddress((void**)&pR,  g_R);
    cudaGetSymbolAddress((void**)&pH,  g_H);
    cudaGetSymbolAddress((void**)&pH2, g_H2);
    cudaGetSymbolAddress((void**)&pH3, g_H3);
    cudaGetSymbolAddress((void**)&pH4, g_H4);

    // CSR build (dtype-robust)
    init_kernel<<<(N_NODES + 255) / 256, 256>>>();
    detect_kernel<<<(N_EDGES + 255) / 256, 256>>>((const long long*)ei);
    count_kernel<<<(N_EDGES + 255) / 256, 256>>>(ei);
    scan_kernel<<<1, 1024>>>();
    scatter_kernel<<<(N_EDGES + 255) / 256, 256>>>(ei);

    const int MBLK = (N_NODES + 127) / 128;   // 79

    // Y = x @ W_l ; R = x @ W_r   (N=256, K=512)
    gemm_kernel<128, 8><<<dim3(2, MBLK), 256>>>(x, W_l, nullptr, pY, N_NODES, 512, 256, 0);
    gemm_kernel<128, 8><<<dim3(2, MBLK), 256>>>(x, W_r, nullptr, pR, N_NODES, 512, 256, 0);

    // H = relu(segmean(Y) + b_l + R)
    aggr_kernel<<<(N_NODES * 32 + 255) / 256, 256>>>(b_l);

    // MLP
    gemm_kernel<128, 8><<<dim3(1, MBLK), 256>>>(pH,  Wa, ba, pH2, N_NODES, 256, 128, 1);
    gemm_kernel<64, 4><<<dim3(1, MBLK), 256>>>(pH2, W1, b1, pH3, N_NODES, 128, 64, 1);
    gemm_kernel<32, 2><<<dim3(1, MBLK), 256>>>(pH3, W2, b2, pH4, N_NODES, 64, 32, 1);
    final_kernel<<<(N_NODES + 255) / 256, 256>>>(W3, b3);

    // pairwise distances
    dist_kernel<<<dim3(MBLK, MBLK), 256>>>(out);

    (void)in_sizes; (void)n_in; (void)out_size;
}